// round 13
// baseline (speedup 1.0000x reference)
#include <cuda_runtime.h>

#define MAXN 100000
#define MAXE 1000000
#define F 64

// Scratch (__device__ globals only; never take their address in host code —
// GB300 ATS silently routes host-shadow addresses over NVLink-C2C, R6 lesson).
// g_degi invariant: zero at entry to every executed kernel_launch (zeroed at
// module load by CUDA, re-zeroed at the end of every call).
__device__ int   g_degi[MAXN];
__device__ int   g_pre[MAXN];
__device__ int   g_bsum[256];
__device__ int   g_rowptr[MAXN];
__device__ int   g_cursor[MAXN];
__device__ int   g_csrc[MAXE];
__device__ float g_hs1[(size_t)MAXN * F];
__device__ float g_acc1[(size_t)MAXN * F];
__device__ float g_hs2[(size_t)MAXN * F];
__device__ float g_acc2[(size_t)MAXN * F];

__global__ void k_deg_count(const int* __restrict__ dst, int E) {
    int e = blockIdx.x * blockDim.x + threadIdx.x;
    if (e < E) atomicAdd(&g_degi[dst[e]], 1);
}

__global__ void k_deg_zero(int N) {
    int i = blockIdx.x * blockDim.x + threadIdx.x;
    if (i < N) g_degi[i] = 0;
}

// ---- CSR build: blockwise inclusive scan of degrees -> rowptr ----
__global__ void k_scan1(int N) {
    __shared__ int s[512];
    int t = threadIdx.x;
    int i = blockIdx.x * 512 + t;
    s[t] = (i < N) ? g_degi[i] : 0;
    __syncthreads();
#pragma unroll
    for (int o = 1; o < 512; o <<= 1) {
        int a = (t >= o) ? s[t - o] : 0;
        __syncthreads();
        s[t] += a;
        __syncthreads();
    }
    if (i < N) g_pre[i] = s[t];
    if (t == 511) g_bsum[blockIdx.x] = s[511];
}

// Fused scan2+scan3: each block reduces bsum[0..b-1] itself, then writes
// rowptr/cursor.
__global__ void k_scan23(int N, int NB) {
    __shared__ int red[512];
    int b = blockIdx.x;
    int t = threadIdx.x;
    red[t] = (t < b && t < NB) ? g_bsum[t] : 0;
    __syncthreads();
#pragma unroll
    for (int o = 256; o > 0; o >>= 1) {
        if (t < o) red[t] += red[t + o];
        __syncthreads();
    }
    int off = red[0];
    int i = b * 512 + t;
    if (i < N) {
        int start = off + g_pre[i] - g_degi[i];  // exclusive prefix
        g_rowptr[i] = start;
        g_cursor[i] = start;
    }
}

__global__ void k_fill(const int* __restrict__ src, const int* __restrict__ dst, int E) {
    int e = blockIdx.x * blockDim.x + threadIdx.x;
    if (e >= E) return;
    int p = atomicAdd(&g_cursor[dst[e]], 1);
    g_csrc[p] = src[e];
}

// ---- Gather (row range [base,end)): acc[n] = hs[n] + sum_neigh hs[s] ----
template <int L>
__global__ void k_gather(int base, int end) {
    const float* hs = (L == 1) ? g_hs1 : g_hs2;
    float* acc = (L == 1) ? g_acc1 : g_acc2;
    int t = blockIdx.x * blockDim.x + threadIdx.x;
    int node = base + (t >> 4);
    if (node >= end) return;
    int c = (t & 15) * 4;
    float4 a = *(const float4*)&hs[(size_t)node * F + c];
    int rp = g_rowptr[node];
    int de = g_degi[node];
    int j = 0;
    for (; j + 1 < de; j += 2) {
        int s0 = g_csrc[rp + j];
        int s1 = g_csrc[rp + j + 1];
        float4 v0 = *(const float4*)&hs[(size_t)s0 * F + c];
        float4 v1 = *(const float4*)&hs[(size_t)s1 * F + c];
        a.x += v0.x; a.y += v0.y; a.z += v0.z; a.w += v0.w;
        a.x += v1.x; a.y += v1.y; a.z += v1.z; a.w += v1.w;
    }
    if (j < de) {
        int s0 = g_csrc[rp + j];
        float4 v0 = *(const float4*)&hs[(size_t)s0 * F + c];
        a.x += v0.x; a.y += v0.y; a.z += v0.z; a.w += v0.w;
    }
    *(float4*)&acc[(size_t)node * F + c] = a;
}

// ---- Fused GEMM over rows [base,end): TM=4 x TN=8 per thread (1.5 B/FMA).
// dinv computed inline from degi (MUFU ~free).
//  MODE 0: in = x[row];                 g_hs1 = (in@W)*dinv
//  MODE 1: in = relu(dinv*g_acc1 + b);  g_hs2 = (in@W)*dinv
//  MODE 2: in = relu(dinv*g_acc2 + b);  out = in@W + b_out   (NOUT=32)
template <int NOUT, int MODE>
__global__ void __launch_bounds__(256, 3)
k_gemm(const float* __restrict__ xin, const float* __restrict__ W,
       const float* __restrict__ b_in, const float* __restrict__ b_out,
       float* __restrict__ out, int base, int end) {
    constexpr int TM = 4, TN = 8;
    constexpr int CPT = NOUT / TN;          // col slices per row (8 or 4)
    constexpr int RPB = (256 / CPT) * TM;   // rows per block (128 or 256)

    __shared__ float sW[F * NOUT];
    __shared__ float sB[F];
    {
        const float4* W4 = (const float4*)W;
        float4* sW4 = (float4*)sW;
        for (int i = threadIdx.x; i < F * NOUT / 4; i += 256) sW4[i] = W4[i];
        if (MODE != 0 && threadIdx.x < F) sB[threadIdx.x] = b_in[threadIdx.x];
    }
    __syncthreads();

    int q  = threadIdx.x % CPT;
    int gl = threadIdx.x / CPT;
    int row0 = base + blockIdx.x * RPB + gl * TM;
    if (row0 >= end) return;

    float acc[TM][TN];
#pragma unroll
    for (int r = 0; r < TM; r++)
#pragma unroll
        for (int j = 0; j < TN; j++) acc[r][j] = 0.0f;

    float dv[TM];
#pragma unroll
    for (int r = 0; r < TM; r++) {
        int row = row0 + r;
        dv[r] = (row < end) ? rsqrtf(1.0f + (float)g_degi[row]) : 0.0f;
    }

    const float* srcbuf = (MODE == 0) ? xin
                        : (MODE == 1) ? (const float*)g_acc1
                                      : (const float*)g_acc2;

#pragma unroll
    for (int kk = 0; kk < F / 4; kk++) {
        float xr[TM][4];
#pragma unroll
        for (int r = 0; r < TM; r++) {
            int row = row0 + r;
            float4 a = make_float4(0.f, 0.f, 0.f, 0.f);
            if (row < end) a = *(const float4*)&srcbuf[(size_t)row * F + kk * 4];
            if (MODE == 0) {
                xr[r][0] = a.x; xr[r][1] = a.y; xr[r][2] = a.z; xr[r][3] = a.w;
            } else {
                float4 bb = *(const float4*)&sB[kk * 4];
                xr[r][0] = fmaxf(fmaf(dv[r], a.x, bb.x), 0.0f);
                xr[r][1] = fmaxf(fmaf(dv[r], a.y, bb.y), 0.0f);
                xr[r][2] = fmaxf(fmaf(dv[r], a.z, bb.z), 0.0f);
                xr[r][3] = fmaxf(fmaf(dv[r], a.w, bb.w), 0.0f);
            }
        }
#pragma unroll
        for (int u = 0; u < 4; u++) {
            const float4* wr = (const float4*)&sW[(kk * 4 + u) * NOUT + q * TN];
            float4 w0 = wr[0], w1 = wr[1];
#pragma unroll
            for (int r = 0; r < TM; r++) {
                float v = xr[r][u];
                acc[r][0] = fmaf(v, w0.x, acc[r][0]);
                acc[r][1] = fmaf(v, w0.y, acc[r][1]);
                acc[r][2] = fmaf(v, w0.z, acc[r][2]);
                acc[r][3] = fmaf(v, w0.w, acc[r][3]);
                acc[r][4] = fmaf(v, w1.x, acc[r][4]);
                acc[r][5] = fmaf(v, w1.y, acc[r][5]);
                acc[r][6] = fmaf(v, w1.z, acc[r][6]);
                acc[r][7] = fmaf(v, w1.w, acc[r][7]);
            }
        }
    }

    if (MODE == 2) {
        const float4* bo4 = (const float4*)(b_out + q * TN);
        float4 bo0 = bo4[0], bo1 = bo4[1];
#pragma unroll
        for (int r = 0; r < TM; r++) {
            int row = row0 + r;
            if (row >= end) break;
            float4* o4 = (float4*)(out + (size_t)row * NOUT + q * TN);
            float4 r0, r1;
            r0.x = acc[r][0] + bo0.x;  r0.y = acc[r][1] + bo0.y;
            r0.z = acc[r][2] + bo0.z;  r0.w = acc[r][3] + bo0.w;
            r1.x = acc[r][4] + bo1.x;  r1.y = acc[r][5] + bo1.y;
            r1.z = acc[r][6] + bo1.z;  r1.w = acc[r][7] + bo1.w;
            o4[0] = r0; o4[1] = r1;
        }
    } else {
        float* hsw = (MODE == 0) ? g_hs1 : g_hs2;
#pragma unroll
        for (int r = 0; r < TM; r++) {
            int row = row0 + r;
            if (row >= end) break;
            float4* h4 = (float4*)(hsw + (size_t)row * F + q * TN);
            float4 r0, r1;
            r0.x = acc[r][0] * dv[r];  r0.y = acc[r][1] * dv[r];
            r0.z = acc[r][2] * dv[r];  r0.w = acc[r][3] * dv[r];
            r1.x = acc[r][4] * dv[r];  r1.y = acc[r][5] * dv[r];
            r1.z = acc[r][6] * dv[r];  r1.w = acc[r][7] * dv[r];
            h4[0] = r0; h4[1] = r1;
        }
    }
}

extern "C" void kernel_launch(void* const* d_in, const int* in_sizes, int n_in,
                              void* d_out, int out_size) {
    const float* x  = (const float*)d_in[0];
    const int*   ei = (const int*)d_in[1];
    const float* W1 = (const float*)d_in[2];
    const float* b1 = (const float*)d_in[3];
    const float* W2 = (const float*)d_in[4];
    const float* b2 = (const float*)d_in[5];
    const float* Wl = (const float*)d_in[6];
    const float* bl = (const float*)d_in[7];
    float* out = (float*)d_out;

    int N = in_sizes[0] / F;
    int E = in_sizes[1] / 2;
    const int* src = ei;
    const int* dst = ei + E;

    int nb256 = (N + 255) / 256;
    int eb    = (E + 255) / 256;
    int nbs   = (N + 511) / 512;

    // half split, aligned to 512 rows (divisible by both GEMM RPBs)
    int NH = ((N / 2 + 511) / 512) * 512;
    if (NH > N) NH = N;
    int nA = NH, nB = N - NH;

    auto gb64 = [](int r) { return (r + 127) / 128; };
    auto gb32 = [](int r) { return (r + 255) / 256; };
    auto gbga = [](int r) { return (r * 16 + 255) / 256; };

    // Fork/join stream (created fresh each call; intentionally not destroyed —
    // can't destroy a forked stream mid-capture; handful of calls per process).
    cudaStream_t s2;
    cudaStreamCreateWithFlags(&s2, cudaStreamNonBlocking);
    cudaEvent_t evDeg, evCsr, evG1, evM2A, evM2B, evM3A, evEnd2;
    cudaEventCreateWithFlags(&evDeg, cudaEventDisableTiming);
    cudaEventCreateWithFlags(&evCsr, cudaEventDisableTiming);
    cudaEventCreateWithFlags(&evG1, cudaEventDisableTiming);
    cudaEventCreateWithFlags(&evM2A, cudaEventDisableTiming);
    cudaEventCreateWithFlags(&evM2B, cudaEventDisableTiming);
    cudaEventCreateWithFlags(&evM3A, cudaEventDisableTiming);
    cudaEventCreateWithFlags(&evEnd2, cudaEventDisableTiming);

    // degree (g_degi is zero at entry by invariant; re-zeroed at end)
    k_deg_count<<<eb, 256>>>(dst, E);
    cudaEventRecord(evDeg, 0);

    // s2: CSR build (needs degree only)
    cudaStreamWaitEvent(s2, evDeg, 0);
    k_scan1<<<nbs, 512, 0, s2>>>(N);
    k_scan23<<<nbs, 512, 0, s2>>>(N, nbs);
    k_fill<<<eb, 256, 0, s2>>>(src, dst, E);
    cudaEventRecord(evCsr, s2);

    // main: gemm1 full (needs degree only; dinv inline)
    k_gemm<F, 0><<<gb64(N), 256>>>(x, W1, nullptr, nullptr, nullptr, 0, N);
    cudaEventRecord(evG1, 0);

    // ---- pipelined halves ----
    // main: gather1_A (needs CSR) -> gemm2_A
    cudaStreamWaitEvent(0, evCsr, 0);
    k_gather<1><<<gbga(nA), 256>>>(0, NH);
    k_gemm<F, 1><<<gb64(nA), 256>>>(nullptr, W2, b1, nullptr, nullptr, 0, NH);
    cudaEventRecord(evM2A, 0);

    // s2: gather1_B (needs full hs1) -> gemm2_B
    cudaStreamWaitEvent(s2, evG1, 0);
    k_gather<1><<<gbga(nB), 256, 0, s2>>>(NH, N);
    k_gemm<F, 1><<<gb64(nB), 256, 0, s2>>>(nullptr, W2, b1, nullptr, nullptr, NH, N);
    cudaEventRecord(evM2B, s2);

    // main: gather2_A (needs full hs2) -> gemm3_A
    cudaStreamWaitEvent(0, evM2B, 0);
    k_gather<2><<<gbga(nA), 256>>>(0, NH);
    k_gemm<32, 2><<<gb32(nA), 256>>>(nullptr, Wl, b2, bl, out, 0, NH);
    cudaEventRecord(evM3A, 0);

    // s2: gather2_B -> gemm3_B -> deg zero (restores invariant; off critical path)
    cudaStreamWaitEvent(s2, evM2A, 0);
    k_gather<2><<<gbga(nB), 256, 0, s2>>>(NH, N);
    k_gemm<32, 2><<<gb32(nB), 256, 0, s2>>>(nullptr, Wl, b2, bl, out, NH, N);
    cudaStreamWaitEvent(s2, evM3A, 0);  // degi read by gemm3_A/gather2_A too
    k_deg_zero<<<nb256, 256, 0, s2>>>(N);
    cudaEventRecord(evEnd2, s2);

    // join
    cudaStreamWaitEvent(0, evEnd2, 0);
}

// round 14
// speedup vs baseline: 1.4293x; 1.4293x over previous
#include <cuda_runtime.h>

#define MAXN 100000
#define MAXE 1000000
#define F 64

// Scratch (__device__ globals only; never take their address in host code —
// GB300 ATS silently routes host-shadow addresses over NVLink-C2C, R6 lesson).
// g_degi invariant: zero at entry to every executed kernel_launch (zeroed at
// module load by CUDA, re-zeroed mid-call on s2 after its last readers).
__device__ int   g_degi[MAXN];
__device__ int   g_pre[MAXN];     // block-exclusive prefix of degrees
__device__ int   g_bsum[256];
__device__ int   g_rowptr[MAXN];  // row start
__device__ int   g_cursor[MAXN];  // after fill: row end (rowptr + deg)
__device__ int   g_csrc[MAXE];
__device__ float g_hs1[(size_t)MAXN * F];
__device__ float g_acc1[(size_t)MAXN * F];
__device__ float g_hs2[(size_t)MAXN * F];
__device__ float g_acc2[(size_t)MAXN * F];

__global__ void k_deg_count(const int* __restrict__ dst, int E) {
    int e = blockIdx.x * blockDim.x + threadIdx.x;
    if (e < E) atomicAdd(&g_degi[dst[e]], 1);
}

__global__ void k_deg_zero(int N) {
    int i = blockIdx.x * blockDim.x + threadIdx.x;
    if (i < N) g_degi[i] = 0;
}

// ---- CSR build ----
// scan1: blockwise inclusive scan; writes EXCLUSIVE prefix (incl - deg) so
// later stages never touch g_degi again.
__global__ void k_scan1(int N) {
    __shared__ int s[512];
    int t = threadIdx.x;
    int i = blockIdx.x * 512 + t;
    int d = (i < N) ? g_degi[i] : 0;
    s[t] = d;
    __syncthreads();
#pragma unroll
    for (int o = 1; o < 512; o <<= 1) {
        int a = (t >= o) ? s[t - o] : 0;
        __syncthreads();
        s[t] += a;
        __syncthreads();
    }
    if (i < N) g_pre[i] = s[t] - d;   // block-exclusive prefix
    if (t == 511) g_bsum[blockIdx.x] = s[511];
}

// scan23: each block reduces bsum[0..b-1], writes rowptr/cursor. No degi read.
__global__ void k_scan23(int N, int NB) {
    __shared__ int red[512];
    int b = blockIdx.x;
    int t = threadIdx.x;
    red[t] = (t < b && t < NB) ? g_bsum[t] : 0;
    __syncthreads();
#pragma unroll
    for (int o = 256; o > 0; o >>= 1) {
        if (t < o) red[t] += red[t + o];
        __syncthreads();
    }
    int off = red[0];
    int i = b * 512 + t;
    if (i < N) {
        int start = off + g_pre[i];
        g_rowptr[i] = start;
        g_cursor[i] = start;
    }
}

__global__ void k_fill(const int* __restrict__ src, const int* __restrict__ dst, int E) {
    int e = blockIdx.x * blockDim.x + threadIdx.x;
    if (e >= E) return;
    int p = atomicAdd(&g_cursor[dst[e]], 1);
    g_csrc[p] = src[e];
}

// ---- Gather: acc[n] = hs[n] + sum_neigh hs[s]. deg = cursor - rowptr. ----
template <int L>
__global__ void k_gather(int N) {
    const float* hs = (L == 1) ? g_hs1 : g_hs2;
    float* acc = (L == 1) ? g_acc1 : g_acc2;
    int t = blockIdx.x * blockDim.x + threadIdx.x;
    int node = t >> 4;
    if (node >= N) return;
    int c = (t & 15) * 4;
    float4 a = *(const float4*)&hs[(size_t)node * F + c];
    int rp = g_rowptr[node];
    int re = g_cursor[node];
    int j = rp;
    for (; j + 1 < re; j += 2) {
        int s0 = g_csrc[j];
        int s1 = g_csrc[j + 1];
        float4 v0 = *(const float4*)&hs[(size_t)s0 * F + c];
        float4 v1 = *(const float4*)&hs[(size_t)s1 * F + c];
        a.x += v0.x; a.y += v0.y; a.z += v0.z; a.w += v0.w;
        a.x += v1.x; a.y += v1.y; a.z += v1.z; a.w += v1.w;
    }
    if (j < re) {
        int s0 = g_csrc[j];
        float4 v0 = *(const float4*)&hs[(size_t)s0 * F + c];
        a.x += v0.x; a.y += v0.y; a.z += v0.z; a.w += v0.w;
    }
    *(float4*)&acc[(size_t)node * F + c] = a;
}

// ---- Fused GEMM: TM=4 x TN=8 per thread (1.5 B/FMA). dinv inline:
//  MODE 0 from g_degi (CSR not ready yet); MODE 1/2 from cursor - rowptr.
//  MODE 0: in = x[row];                 g_hs1 = (in@W)*dinv
//  MODE 1: in = relu(dinv*g_acc1 + b);  g_hs2 = (in@W)*dinv
//  MODE 2: in = relu(dinv*g_acc2 + b);  out = in@W + b_out   (NOUT=32)
template <int NOUT, int MODE>
__global__ void __launch_bounds__(256, 3)
k_gemm(const float* __restrict__ xin, const float* __restrict__ W,
       const float* __restrict__ b_in, const float* __restrict__ b_out,
       float* __restrict__ out, int N) {
    constexpr int TM = 4, TN = 8;
    constexpr int CPT = NOUT / TN;          // col slices per row (8 or 4)
    constexpr int RPB = (256 / CPT) * TM;   // rows per block (128 or 256)

    __shared__ float sW[F * NOUT];
    __shared__ float sB[F];
    {
        const float4* W4 = (const float4*)W;
        float4* sW4 = (float4*)sW;
        for (int i = threadIdx.x; i < F * NOUT / 4; i += 256) sW4[i] = W4[i];
        if (MODE != 0 && threadIdx.x < F) sB[threadIdx.x] = b_in[threadIdx.x];
    }
    __syncthreads();

    int q  = threadIdx.x % CPT;
    int gl = threadIdx.x / CPT;
    int row0 = blockIdx.x * RPB + gl * TM;
    if (row0 >= N) return;

    float acc[TM][TN];
#pragma unroll
    for (int r = 0; r < TM; r++)
#pragma unroll
        for (int j = 0; j < TN; j++) acc[r][j] = 0.0f;

    float dv[TM];
#pragma unroll
    for (int r = 0; r < TM; r++) {
        int row = row0 + r;
        if (row < N) {
            int de = (MODE == 0) ? g_degi[row] : (g_cursor[row] - g_rowptr[row]);
            dv[r] = rsqrtf(1.0f + (float)de);
        } else {
            dv[r] = 0.0f;
        }
    }

    const float* srcbuf = (MODE == 0) ? xin
                        : (MODE == 1) ? (const float*)g_acc1
                                      : (const float*)g_acc2;

#pragma unroll
    for (int kk = 0; kk < F / 4; kk++) {
        float xr[TM][4];
#pragma unroll
        for (int r = 0; r < TM; r++) {
            int row = row0 + r;
            float4 a = make_float4(0.f, 0.f, 0.f, 0.f);
            if (row < N) a = *(const float4*)&srcbuf[(size_t)row * F + kk * 4];
            if (MODE == 0) {
                xr[r][0] = a.x; xr[r][1] = a.y; xr[r][2] = a.z; xr[r][3] = a.w;
            } else {
                float4 bb = *(const float4*)&sB[kk * 4];
                xr[r][0] = fmaxf(fmaf(dv[r], a.x, bb.x), 0.0f);
                xr[r][1] = fmaxf(fmaf(dv[r], a.y, bb.y), 0.0f);
                xr[r][2] = fmaxf(fmaf(dv[r], a.z, bb.z), 0.0f);
                xr[r][3] = fmaxf(fmaf(dv[r], a.w, bb.w), 0.0f);
            }
        }
#pragma unroll
        for (int u = 0; u < 4; u++) {
            const float4* wr = (const float4*)&sW[(kk * 4 + u) * NOUT + q * TN];
            float4 w0 = wr[0], w1 = wr[1];
#pragma unroll
            for (int r = 0; r < TM; r++) {
                float v = xr[r][u];
                acc[r][0] = fmaf(v, w0.x, acc[r][0]);
                acc[r][1] = fmaf(v, w0.y, acc[r][1]);
                acc[r][2] = fmaf(v, w0.z, acc[r][2]);
                acc[r][3] = fmaf(v, w0.w, acc[r][3]);
                acc[r][4] = fmaf(v, w1.x, acc[r][4]);
                acc[r][5] = fmaf(v, w1.y, acc[r][5]);
                acc[r][6] = fmaf(v, w1.z, acc[r][6]);
                acc[r][7] = fmaf(v, w1.w, acc[r][7]);
            }
        }
    }

    if (MODE == 2) {
        const float4* bo4 = (const float4*)(b_out + q * TN);
        float4 bo0 = bo4[0], bo1 = bo4[1];
#pragma unroll
        for (int r = 0; r < TM; r++) {
            int row = row0 + r;
            if (row >= N) break;
            float4* o4 = (float4*)(out + (size_t)row * NOUT + q * TN);
            float4 r0, r1;
            r0.x = acc[r][0] + bo0.x;  r0.y = acc[r][1] + bo0.y;
            r0.z = acc[r][2] + bo0.z;  r0.w = acc[r][3] + bo0.w;
            r1.x = acc[r][4] + bo1.x;  r1.y = acc[r][5] + bo1.y;
            r1.z = acc[r][6] + bo1.z;  r1.w = acc[r][7] + bo1.w;
            o4[0] = r0; o4[1] = r1;
        }
    } else {
        float* hsw = (MODE == 0) ? g_hs1 : g_hs2;
#pragma unroll
        for (int r = 0; r < TM; r++) {
            int row = row0 + r;
            if (row >= N) break;
            float4* h4 = (float4*)(hsw + (size_t)row * F + q * TN);
            float4 r0, r1;
            r0.x = acc[r][0] * dv[r];  r0.y = acc[r][1] * dv[r];
            r0.z = acc[r][2] * dv[r];  r0.w = acc[r][3] * dv[r];
            r1.x = acc[r][4] * dv[r];  r1.y = acc[r][5] * dv[r];
            r1.z = acc[r][6] * dv[r];  r1.w = acc[r][7] * dv[r];
            h4[0] = r0; h4[1] = r1;
        }
    }
}

extern "C" void kernel_launch(void* const* d_in, const int* in_sizes, int n_in,
                              void* d_out, int out_size) {
    const float* x  = (const float*)d_in[0];
    const int*   ei = (const int*)d_in[1];
    const float* W1 = (const float*)d_in[2];
    const float* b1 = (const float*)d_in[3];
    const float* W2 = (const float*)d_in[4];
    const float* b2 = (const float*)d_in[5];
    const float* Wl = (const float*)d_in[6];
    const float* bl = (const float*)d_in[7];
    float* out = (float*)d_out;

    int N = in_sizes[0] / F;
    int E = in_sizes[1] / 2;
    const int* src = ei;
    const int* dst = ei + E;

    int nb256 = (N + 255) / 256;
    int eb    = (E + 255) / 256;
    int nbs   = (N + 511) / 512;
    int gb64  = (N + 127) / 128;
    int gb32  = (N + 255) / 256;
    int gab   = (N * 16 + 255) / 256;

    // Fork/join stream (created fresh each call; intentionally not destroyed —
    // can't destroy a forked stream mid-capture; handful of calls per process).
    cudaStream_t s2;
    cudaStreamCreateWithFlags(&s2, cudaStreamNonBlocking);
    cudaEvent_t evDeg, evCsr, evG1, evZero;
    cudaEventCreateWithFlags(&evDeg, cudaEventDisableTiming);
    cudaEventCreateWithFlags(&evCsr, cudaEventDisableTiming);
    cudaEventCreateWithFlags(&evG1, cudaEventDisableTiming);
    cudaEventCreateWithFlags(&evZero, cudaEventDisableTiming);

    // degree (g_degi zero at entry by invariant)
    k_deg_count<<<eb, 256>>>(dst, E);
    cudaEventRecord(evDeg, 0);

    // s2: CSR build (reads degi only in scan1), then re-zero degi once its
    // last readers (scan1 on s2, gemm1 on main) are done — hidden under gather1.
    cudaStreamWaitEvent(s2, evDeg, 0);
    k_scan1<<<nbs, 512, 0, s2>>>(N);
    k_scan23<<<nbs, 512, 0, s2>>>(N, nbs);
    k_fill<<<eb, 256, 0, s2>>>(src, dst, E);
    cudaEventRecord(evCsr, s2);

    // main: gemm1 full (reads degi for inline dinv)
    k_gemm<F, 0><<<gb64, 256>>>(x, W1, nullptr, nullptr, nullptr, N);
    cudaEventRecord(evG1, 0);

    // s2: restore degi=0 invariant (after scan1 [stream order] and gemm1 [event])
    cudaStreamWaitEvent(s2, evG1, 0);
    k_deg_zero<<<nb256, 256, 0, s2>>>(N);
    cudaEventRecord(evZero, s2);

    // main chain: gather1 -> gemm2 -> gather2 -> gemm3 (deg from cursor-rowptr)
    cudaStreamWaitEvent(0, evCsr, 0);
    k_gather<1><<<gab, 256>>>(N);
    k_gemm<F, 1><<<gb64, 256>>>(nullptr, W2, b1, nullptr, nullptr, N);
    k_gather<2><<<gab, 256>>>(N);
    k_gemm<32, 2><<<gb32, 256>>>(nullptr, Wl, b2, bl, out, N);

    // join: ensure the zeroing is inside the captured graph
    cudaStreamWaitEvent(0, evZero, 0);
}